// round 15
// baseline (speedup 1.0000x reference)
#include <cuda_runtime.h>
#include <math.h>

#define NN 100000
#define EE 1000000
#define HC 80
#define ED 16

// ---------------- device scratch (static, no allocation) ----------------
static __device__ int   g_cnt[NN];        // zero-init; scan_a re-zeroes each run
static __device__ int   g_rowptr[NN + 1];
static __device__ int   g_wp[NN];
static __device__ int   g_srcs[EE];
static __device__ float g_eatt[EE * ED];  // edge_attr permuted into CSR order
static __device__ float g_xl[NN * HC];
static __device__ float g_xr[NN * HC];
static __device__ float g_h[NN * HC];
static __device__ int   g_scanbuf[NN];
static __device__ int   g_part[256];

// ---------------- CSR build ----------------
__global__ void hist_kernel(const int* __restrict__ dst) {
    int e = blockIdx.x * blockDim.x + threadIdx.x;
    if (e < EE) atomicAdd(&g_cnt[dst[e]], 1);
}

__global__ void scan_a_kernel() {
    __shared__ int s[512];
    int t = threadIdx.x;
    int i = blockIdx.x * 512 + t;
    int v = (i < NN) ? g_cnt[i] : 0;
    if (i < NN) g_cnt[i] = 0;          // self-clear for next graph replay
    s[t] = v;
    __syncthreads();
    for (int off = 1; off < 512; off <<= 1) {
        int x = (t >= off) ? s[t - off] : 0;
        __syncthreads();
        s[t] += x;
        __syncthreads();
    }
    if (i < NN) g_scanbuf[i] = s[t] - v;   // exclusive within block
    if (t == 511) g_part[blockIdx.x] = s[511];
}

// merged scan_b + scan_c: every block redundantly scans the 196 partials
__global__ void scan_bc_kernel(int nb) {
    __shared__ int sp[512];
    __shared__ int off0;
    int t = threadIdx.x;
    int v = (t < nb) ? g_part[t] : 0;
    sp[t] = v;
    __syncthreads();
    for (int off = 1; off < 256; off <<= 1) {
        int x = (t >= off) ? sp[t - off] : 0;
        __syncthreads();
        sp[t] += x;
        __syncthreads();
    }
    if (t == blockIdx.x) off0 = sp[t] - v;   // exclusive prefix of this block
    __syncthreads();
    int i = blockIdx.x * 512 + t;
    if (i < NN) {
        int r = g_scanbuf[i] + off0;
        g_rowptr[i] = r;
        g_wp[i] = r;
    }
    if (i == 0) g_rowptr[NN] = EE;
}

// fill CSR arrays AND permute edge_attr into CSR order (coalesced later reads)
__global__ void fill_kernel(const int* __restrict__ src, const int* __restrict__ dst,
                            const float* __restrict__ eattr) {
    int e = blockIdx.x * blockDim.x + threadIdx.x;
    if (e >= EE) return;
    int d = dst[e];
    int p = atomicAdd(&g_wp[d], 1);
    g_srcs[p] = src[e];
    const float4* ev = (const float4*)(eattr + (size_t)e * ED);
    float4* ov = (float4*)(g_eatt + (size_t)p * ED);
    ov[0] = ev[0];
    ov[1] = ev[1];
    ov[2] = ev[2];
    ov[3] = ev[3];
}

// ---------------- node transform: xl = X@wl.T + bl ; xr = X@wr.T + br -------
// 160 threads; cg = tid>>2 (40 groups x 4 cols), rg = tid&3; thread does
// 8 rows {rg, rg+4, ..., rg+28} x 4 cols, XOR-swizzled xs -> conflict-free LDS.
__global__ void __launch_bounds__(160)
gemm_lr_kernel(const float* __restrict__ Xin, int use_gh, int K,
               const float* __restrict__ wl, const float* __restrict__ bl,
               const float* __restrict__ wr, const float* __restrict__ br) {
    __shared__ __align__(16) float xs[32 * 128];   // 16 KB, pitch 128 floats
    const float* X = use_gh ? g_h : Xin;
    int row0 = blockIdx.x * 32;
    int tid = threadIdx.x;
    int k4n = K >> 2;                               // chunks per row (32 or 20)

    {
        const float4* Xv = (const float4*)(X + (size_t)row0 * K);
        float4* xsv = (float4*)xs;
        int n4 = 32 * k4n;
        for (int i = tid; i < n4; i += 160) {
            int r = i / k4n, kk = i - r * k4n;
            xsv[r * 32 + (kk ^ (r & 7))] = Xv[i];
        }
    }
    __syncthreads();

    int cg = tid >> 2;        // 0..39
    int rg = tid & 3;         // 0..3
    int c0 = cg * 4;
    bool left = (c0 < HC);
    const float* w  = left ? wl : wr;
    const float* bv = left ? bl : br;
    int cc = left ? c0 : c0 - HC;
    const float* w0 = w + (size_t)(cc + 0) * K;
    const float* w1 = w + (size_t)(cc + 1) * K;
    const float* w2 = w + (size_t)(cc + 2) * K;
    const float* w3 = w + (size_t)(cc + 3) * K;

    float acc[8][4];
#pragma unroll
    for (int r = 0; r < 8; r++)
#pragma unroll
        for (int c = 0; c < 4; c++) acc[r][c] = 0.f;

    const float4* xsv = (const float4*)xs;
    for (int k4 = 0; k4 < k4n; k4++) {
        int k = k4 * 4;
        float4 wa = *(const float4*)(w0 + k);
        float4 wb = *(const float4*)(w1 + k);
        float4 wc = *(const float4*)(w2 + k);
        float4 wd = *(const float4*)(w3 + k);
#pragma unroll
        for (int r = 0; r < 8; r++) {
            int row = rg + r * 4;                   // row & 7 = rg or rg+4
            float4 xv = xsv[row * 32 + (k4 ^ (row & 7))];
            acc[r][0] += xv.x * wa.x + xv.y * wa.y + xv.z * wa.z + xv.w * wa.w;
            acc[r][1] += xv.x * wb.x + xv.y * wb.y + xv.z * wb.z + xv.w * wb.w;
            acc[r][2] += xv.x * wc.x + xv.y * wc.y + xv.z * wc.z + xv.w * wc.w;
            acc[r][3] += xv.x * wd.x + xv.y * wd.y + xv.z * wd.z + xv.w * wd.w;
        }
    }

    float4 b4 = *(const float4*)(bv + cc);
    float* dstbuf = left ? g_xl : g_xr;
#pragma unroll
    for (int r = 0; r < 8; r++) {
        int row = row0 + rg + r * 4;
        float4 o;
        o.x = acc[r][0] + b4.x;
        o.y = acc[r][1] + b4.y;
        o.z = acc[r][2] + b4.z;
        o.w = acc[r][3] + b4.w;
        *(float4*)(dstbuf + (size_t)row * HC + cc) = o;
    }
}

// ---------------- fused edge-score + softmax + aggregate --------------------
// One warp per destination node; lanes 0..19 (head h = lane/4, 4 channels).
// Shift-free softmax (alpha statistically bounded << 88; fixed shift cancels
// in num/den) -> accumulators are plain adds -> trivially unrollable.
// 4-WAY UNROLL: 4 independent src loads + 4 xl gathers + 8 eatt LDG.128 in
// flight per iteration (MLP~4) to hide the L2 gather latency that dominates.
__global__ void __launch_bounds__(256)
fused_attn_kernel(const float* __restrict__ we,
                  const float* __restrict__ att,
                  const float* __restrict__ bias,
                  float* __restrict__ out, int out_sel, int apply_relu) {
    __shared__ __align__(16) float wet[ED * HC];  // wet[k*80+c] = we[c*16+k]
    __shared__ __align__(16) float satt[HC];
    int tid = threadIdx.x;
    for (int i = tid; i < ED * HC; i += blockDim.x) {
        int c = i >> 4, k = i & 15;
        wet[k * HC + c] = we[i];
    }
    for (int i = tid; i < HC; i += blockDim.x) satt[i] = att[i];
    __syncthreads();

    int lane = tid & 31;
    int d = blockIdx.x * (blockDim.x >> 5) + (tid >> 5);
    if (lane >= 20 || d >= NN) return;
    const unsigned MASK = 0x000FFFFFu;
    int c0 = lane * 4;

    float4 wreg[ED];
#pragma unroll
    for (int k = 0; k < ED; k++) wreg[k] = *(const float4*)(wet + k * HC + c0);
    float4 a4  = *(const float4*)(satt + c0);
    float4 xr4 = *(const float4*)(g_xr + (size_t)d * HC + c0);

    int st = g_rowptr[d];
    int en = g_rowptr[d + 1];

    float den = 0.f;
    float4 acc = {0.f, 0.f, 0.f, 0.f};

    int j = st;
    for (; j + 3 < en; j += 4) {
        // 4 independent index loads + gathers (MLP)
        int s0 = g_srcs[j + 0];
        int s1 = g_srcs[j + 1];
        int s2 = g_srcs[j + 2];
        int s3 = g_srcs[j + 3];
        float4 xl0 = *(const float4*)(g_xl + (size_t)s0 * HC + c0);
        float4 xl1 = *(const float4*)(g_xl + (size_t)s1 * HC + c0);
        float4 xl2 = *(const float4*)(g_xl + (size_t)s2 * HC + c0);
        float4 xl3 = *(const float4*)(g_xl + (size_t)s3 * HC + c0);
        const float4* eP = (const float4*)(g_eatt + (size_t)j * ED);

        float4 m0, m1, m2, m3;
        m0.x = xl0.x + xr4.x; m0.y = xl0.y + xr4.y; m0.z = xl0.z + xr4.z; m0.w = xl0.w + xr4.w;
        m1.x = xl1.x + xr4.x; m1.y = xl1.y + xr4.y; m1.z = xl1.z + xr4.z; m1.w = xl1.w + xr4.w;
        m2.x = xl2.x + xr4.x; m2.y = xl2.y + xr4.y; m2.z = xl2.z + xr4.z; m2.w = xl2.w + xr4.w;
        m3.x = xl3.x + xr4.x; m3.y = xl3.y + xr4.y; m3.z = xl3.z + xr4.z; m3.w = xl3.w + xr4.w;

#pragma unroll
        for (int q = 0; q < 4; q++) {
            float4 e0 = eP[q];          // edge j   attrs [4q..4q+3]
            float4 e1 = eP[q + 4];      // edge j+1
            float4 e2 = eP[q + 8];      // edge j+2
            float4 e3 = eP[q + 12];     // edge j+3
#pragma unroll
            for (int u = 0; u < 4; u++) {
                float4 wk = wreg[q * 4 + u];
                float a0 = (u == 0) ? e0.x : (u == 1) ? e0.y : (u == 2) ? e0.z : e0.w;
                float a1 = (u == 0) ? e1.x : (u == 1) ? e1.y : (u == 2) ? e1.z : e1.w;
                float a2 = (u == 0) ? e2.x : (u == 1) ? e2.y : (u == 2) ? e2.z : e2.w;
                float a3 = (u == 0) ? e3.x : (u == 1) ? e3.y : (u == 2) ? e3.z : e3.w;
                m0.x += a0 * wk.x; m0.y += a0 * wk.y; m0.z += a0 * wk.z; m0.w += a0 * wk.w;
                m1.x += a1 * wk.x; m1.y += a1 * wk.y; m1.z += a1 * wk.z; m1.w += a1 * wk.w;
                m2.x += a2 * wk.x; m2.y += a2 * wk.y; m2.z += a2 * wk.z; m2.w += a2 * wk.w;
                m3.x += a3 * wk.x; m3.y += a3 * wk.y; m3.z += a3 * wk.z; m3.w += a3 * wk.w;
            }
        }

#define LRELU4(mm) \
        mm.x = (mm.x > 0.f) ? mm.x : 0.2f * mm.x; \
        mm.y = (mm.y > 0.f) ? mm.y : 0.2f * mm.y; \
        mm.z = (mm.z > 0.f) ? mm.z : 0.2f * mm.z; \
        mm.w = (mm.w > 0.f) ? mm.w : 0.2f * mm.w;
        LRELU4(m0) LRELU4(m1) LRELU4(m2) LRELU4(m3)

        float p0 = m0.x * a4.x + m0.y * a4.y + m0.z * a4.z + m0.w * a4.w;
        float p1 = m1.x * a4.x + m1.y * a4.y + m1.z * a4.z + m1.w * a4.w;
        float p2 = m2.x * a4.x + m2.y * a4.y + m2.z * a4.z + m2.w * a4.w;
        float p3 = m3.x * a4.x + m3.y * a4.y + m3.z * a4.z + m3.w * a4.w;
        p0 += __shfl_xor_sync(MASK, p0, 1);
        p1 += __shfl_xor_sync(MASK, p1, 1);
        p2 += __shfl_xor_sync(MASK, p2, 1);
        p3 += __shfl_xor_sync(MASK, p3, 1);
        p0 += __shfl_xor_sync(MASK, p0, 2);
        p1 += __shfl_xor_sync(MASK, p1, 2);
        p2 += __shfl_xor_sync(MASK, p2, 2);
        p3 += __shfl_xor_sync(MASK, p3, 2);

        float e0v = __expf(p0);
        float e1v = __expf(p1);
        float e2v = __expf(p2);
        float e3v = __expf(p3);
        den += e0v + e1v + e2v + e3v;
        acc.x += e0v * xl0.x + e1v * xl1.x + e2v * xl2.x + e3v * xl3.x;
        acc.y += e0v * xl0.y + e1v * xl1.y + e2v * xl2.y + e3v * xl3.y;
        acc.z += e0v * xl0.z + e1v * xl1.z + e2v * xl2.z + e3v * xl3.z;
        acc.w += e0v * xl0.w + e1v * xl1.w + e2v * xl2.w + e3v * xl3.w;
    }

    for (; j < en; j++) {   // remainder (0-3 edges)
        int s = g_srcs[j];
        const float4* eP = (const float4*)(g_eatt + (size_t)j * ED);
        float4 xl4 = *(const float4*)(g_xl + (size_t)s * HC + c0);
        float4 m;
        m.x = xl4.x + xr4.x; m.y = xl4.y + xr4.y;
        m.z = xl4.z + xr4.z; m.w = xl4.w + xr4.w;
#pragma unroll
        for (int q = 0; q < 4; q++) {
            float4 ea = eP[q];
#pragma unroll
            for (int u = 0; u < 4; u++) {
                float av = (u == 0) ? ea.x : (u == 1) ? ea.y : (u == 2) ? ea.z : ea.w;
                float4 wk = wreg[q * 4 + u];
                m.x += av * wk.x; m.y += av * wk.y;
                m.z += av * wk.z; m.w += av * wk.w;
            }
        }
        LRELU4(m)
        float p = m.x * a4.x + m.y * a4.y + m.z * a4.z + m.w * a4.w;
        p += __shfl_xor_sync(MASK, p, 1);
        p += __shfl_xor_sync(MASK, p, 2);
        float a = __expf(p);
        den += a;
        acc.x += a * xl4.x;
        acc.y += a * xl4.y;
        acc.z += a * xl4.z;
        acc.w += a * xl4.w;
    }
#undef LRELU4

    float inv = 1.f / (den + 1e-16f);
    float4 b4 = *(const float4*)(bias + c0);
    float4 o;
    o.x = acc.x * inv + b4.x;
    o.y = acc.y * inv + b4.y;
    o.z = acc.z * inv + b4.z;
    o.w = acc.w * inv + b4.w;
    if (apply_relu) {
        o.x = fmaxf(o.x, 0.f);
        o.y = fmaxf(o.y, 0.f);
        o.z = fmaxf(o.z, 0.f);
        o.w = fmaxf(o.w, 0.f);
    }
    float* obuf = out_sel ? out : g_h;
    *(float4*)(obuf + (size_t)d * HC + c0) = o;
}

// ---------------- launch ----------------
extern "C" void kernel_launch(void* const* d_in, const int* in_sizes, int n_in,
                              void* d_out, int out_size) {
    int ix, iei, iea;
    int iwl[3], ibl[3], iwr[3], ibr[3], iwe[3], iatt[3], ibias[3];
    if (in_sizes[0] == NN * 128) {
        // insertion order: x, edge_index, edge_attr, {wl,bl,wr,br,we,att,bias}x3
        ix = 0; iei = 1; iea = 2;
        for (int l = 0; l < 3; l++) {
            int b = 3 + l * 7;
            iwl[l] = b + 0; ibl[l] = b + 1; iwr[l] = b + 2; ibr[l] = b + 3;
            iwe[l] = b + 4; iatt[l] = b + 5; ibias[l] = b + 6;
        }
    } else {
        // alphabetical: att1-3, b1l,b1r,b2l,b2r,b3l,b3r, bias1-3,
        //               edge_attr, edge_index, (w1e,w1l,w1r)x3, x
        for (int l = 0; l < 3; l++) {
            iatt[l]  = l;
            ibl[l]   = 3 + 2 * l;
            ibr[l]   = 4 + 2 * l;
            ibias[l] = 9 + l;
            iwe[l]   = 14 + 3 * l;
            iwl[l]   = 15 + 3 * l;
            iwr[l]   = 16 + 3 * l;
        }
        iea = 12; iei = 13; ix = 23;
    }

    const float* x      = (const float*)d_in[ix];
    const int*   eindex = (const int*)d_in[iei];     // [2,E] row-major
    const float* eattr  = (const float*)d_in[iea];
    const int* src = eindex;
    const int* dst = eindex + EE;
    float* out = (float*)d_out;

    int nb = (NN + 511) / 512;  // 196

    // launch order keeps gemm_lr layer 0 at index 3 (the ncu-captured launch)
    hist_kernel<<<(EE + 255) / 256, 256>>>(dst);                 // 0
    scan_a_kernel<<<nb, 512>>>();                                // 1
    scan_bc_kernel<<<nb, 512>>>(nb);                             // 2

    gemm_lr_kernel<<<NN / 32, 160>>>(                            // 3 (profiled)
        x, 0, 128,
        (const float*)d_in[iwl[0]], (const float*)d_in[ibl[0]],
        (const float*)d_in[iwr[0]], (const float*)d_in[ibr[0]]);

    fill_kernel<<<(EE + 255) / 256, 256>>>(src, dst, eattr);     // 4

    for (int l = 0; l < 3; l++) {
        const float* we_   = (const float*)d_in[iwe[l]];
        const float* att_  = (const float*)d_in[iatt[l]];
        const float* bias_ = (const float*)d_in[ibias[l]];

        if (l > 0) {
            gemm_lr_kernel<<<NN / 32, 160>>>(
                (const float*)nullptr, 1, HC,
                (const float*)d_in[iwl[l]], (const float*)d_in[ibl[l]],
                (const float*)d_in[iwr[l]], (const float*)d_in[ibr[l]]);
        }
        fused_attn_kernel<<<(NN + 7) / 8, 256>>>(we_, att_, bias_, out,
            (l == 2) ? 1 : 0, (l < 2) ? 1 : 0);
    }
}

// round 16
// speedup vs baseline: 1.9846x; 1.9846x over previous
#include <cuda_runtime.h>
#include <math.h>

#define NN 100000
#define EE 1000000
#define HC 80
#define ED 16

// ---------------- device scratch (static, no allocation) ----------------
static __device__ int   g_cnt[NN];        // zero-init; scan_a re-zeroes each run
static __device__ int   g_rowptr[NN + 1];
static __device__ int   g_wp[NN];
static __device__ int   g_srcs[EE];
static __device__ float g_eatt[EE * ED];  // edge_attr permuted into CSR order
static __device__ float g_xl[NN * HC];
static __device__ float g_xr[NN * HC];
static __device__ float g_h[NN * HC];
static __device__ int   g_scanbuf[NN];
static __device__ int   g_part[256];

// ---------------- CSR build ----------------
__global__ void hist_kernel(const int* __restrict__ dst) {
    int e = blockIdx.x * blockDim.x + threadIdx.x;
    if (e < EE) atomicAdd(&g_cnt[dst[e]], 1);
}

__global__ void scan_a_kernel() {
    __shared__ int s[512];
    int t = threadIdx.x;
    int i = blockIdx.x * 512 + t;
    int v = (i < NN) ? g_cnt[i] : 0;
    if (i < NN) g_cnt[i] = 0;          // self-clear for next graph replay
    s[t] = v;
    __syncthreads();
    for (int off = 1; off < 512; off <<= 1) {
        int x = (t >= off) ? s[t - off] : 0;
        __syncthreads();
        s[t] += x;
        __syncthreads();
    }
    if (i < NN) g_scanbuf[i] = s[t] - v;   // exclusive within block
    if (t == 511) g_part[blockIdx.x] = s[511];
}

// merged scan_b + scan_c: every block redundantly scans the 196 partials
__global__ void scan_bc_kernel(int nb) {
    __shared__ int sp[512];
    __shared__ int off0;
    int t = threadIdx.x;
    int v = (t < nb) ? g_part[t] : 0;
    sp[t] = v;
    __syncthreads();
    for (int off = 1; off < 256; off <<= 1) {
        int x = (t >= off) ? sp[t - off] : 0;
        __syncthreads();
        sp[t] += x;
        __syncthreads();
    }
    if (t == blockIdx.x) off0 = sp[t] - v;   // exclusive prefix of this block
    __syncthreads();
    int i = blockIdx.x * 512 + t;
    if (i < NN) {
        int r = g_scanbuf[i] + off0;
        g_rowptr[i] = r;
        g_wp[i] = r;
    }
    if (i == 0) g_rowptr[NN] = EE;
}

// fill CSR arrays AND permute edge_attr into CSR order (coalesced later reads)
__global__ void fill_kernel(const int* __restrict__ src, const int* __restrict__ dst,
                            const float* __restrict__ eattr) {
    int e = blockIdx.x * blockDim.x + threadIdx.x;
    if (e >= EE) return;
    int d = dst[e];
    int p = atomicAdd(&g_wp[d], 1);
    g_srcs[p] = src[e];
    const float4* ev = (const float4*)(eattr + (size_t)e * ED);
    float4* ov = (float4*)(g_eatt + (size_t)p * ED);
    ov[0] = ev[0];
    ov[1] = ev[1];
    ov[2] = ev[2];
    ov[3] = ev[3];
}

// ---------------- node transform: xl = X@wl.T + bl ; xr = X@wr.T + br -------
// 160 threads; cg = tid>>2 (40 groups x 4 cols), rg = tid&3; thread does
// 8 rows {rg, rg+4, ..., rg+28} x 4 cols, XOR-swizzled xs -> conflict-free LDS.
__global__ void __launch_bounds__(160)
gemm_lr_kernel(const float* __restrict__ Xin, int use_gh, int K,
               const float* __restrict__ wl, const float* __restrict__ bl,
               const float* __restrict__ wr, const float* __restrict__ br) {
    __shared__ __align__(16) float xs[32 * 128];   // 16 KB, pitch 128 floats
    const float* X = use_gh ? g_h : Xin;
    int row0 = blockIdx.x * 32;
    int tid = threadIdx.x;
    int k4n = K >> 2;                               // chunks per row (32 or 20)

    {
        const float4* Xv = (const float4*)(X + (size_t)row0 * K);
        float4* xsv = (float4*)xs;
        int n4 = 32 * k4n;
        for (int i = tid; i < n4; i += 160) {
            int r = i / k4n, kk = i - r * k4n;
            xsv[r * 32 + (kk ^ (r & 7))] = Xv[i];
        }
    }
    __syncthreads();

    int cg = tid >> 2;        // 0..39
    int rg = tid & 3;         // 0..3
    int c0 = cg * 4;
    bool left = (c0 < HC);
    const float* w  = left ? wl : wr;
    const float* bv = left ? bl : br;
    int cc = left ? c0 : c0 - HC;
    const float* w0 = w + (size_t)(cc + 0) * K;
    const float* w1 = w + (size_t)(cc + 1) * K;
    const float* w2 = w + (size_t)(cc + 2) * K;
    const float* w3 = w + (size_t)(cc + 3) * K;

    float acc[8][4];
#pragma unroll
    for (int r = 0; r < 8; r++)
#pragma unroll
        for (int c = 0; c < 4; c++) acc[r][c] = 0.f;

    const float4* xsv = (const float4*)xs;
    for (int k4 = 0; k4 < k4n; k4++) {
        int k = k4 * 4;
        float4 wa = *(const float4*)(w0 + k);
        float4 wb = *(const float4*)(w1 + k);
        float4 wc = *(const float4*)(w2 + k);
        float4 wd = *(const float4*)(w3 + k);
#pragma unroll
        for (int r = 0; r < 8; r++) {
            int row = rg + r * 4;                   // row & 7 = rg or rg+4
            float4 xv = xsv[row * 32 + (k4 ^ (row & 7))];
            acc[r][0] += xv.x * wa.x + xv.y * wa.y + xv.z * wa.z + xv.w * wa.w;
            acc[r][1] += xv.x * wb.x + xv.y * wb.y + xv.z * wb.z + xv.w * wb.w;
            acc[r][2] += xv.x * wc.x + xv.y * wc.y + xv.z * wc.z + xv.w * wc.w;
            acc[r][3] += xv.x * wd.x + xv.y * wd.y + xv.z * wd.z + xv.w * wd.w;
        }
    }

    float4 b4 = *(const float4*)(bv + cc);
    float* dstbuf = left ? g_xl : g_xr;
#pragma unroll
    for (int r = 0; r < 8; r++) {
        int row = row0 + rg + r * 4;
        float4 o;
        o.x = acc[r][0] + b4.x;
        o.y = acc[r][1] + b4.y;
        o.z = acc[r][2] + b4.z;
        o.w = acc[r][3] + b4.w;
        *(float4*)(dstbuf + (size_t)row * HC + cc) = o;
    }
}

// ---------------- fused edge-score + softmax + aggregate --------------------
// One warp per destination node; lanes 0..19 (head h = lane/4, 4 channels).
// Shift-free softmax (alpha statistically bounded << 88; fixed shift cancels
// in num/den) -> accumulators are plain adds -> cheap unrolling.
// 2-WAY UNROLL (measured sweet spot): two independent src loads + xl gathers
// + eatt LDG.128s in flight (MLP~2) without crossing the register cliff.
__global__ void __launch_bounds__(256)
fused_attn_kernel(const float* __restrict__ we,
                  const float* __restrict__ att,
                  const float* __restrict__ bias,
                  float* __restrict__ out, int out_sel, int apply_relu) {
    __shared__ __align__(16) float wet[ED * HC];  // wet[k*80+c] = we[c*16+k]
    __shared__ __align__(16) float satt[HC];
    int tid = threadIdx.x;
    for (int i = tid; i < ED * HC; i += blockDim.x) {
        int c = i >> 4, k = i & 15;
        wet[k * HC + c] = we[i];
    }
    for (int i = tid; i < HC; i += blockDim.x) satt[i] = att[i];
    __syncthreads();

    int lane = tid & 31;
    int d = blockIdx.x * (blockDim.x >> 5) + (tid >> 5);
    if (lane >= 20 || d >= NN) return;
    const unsigned MASK = 0x000FFFFFu;
    int c0 = lane * 4;

    float4 wreg[ED];
#pragma unroll
    for (int k = 0; k < ED; k++) wreg[k] = *(const float4*)(wet + k * HC + c0);
    float4 a4  = *(const float4*)(satt + c0);
    float4 xr4 = *(const float4*)(g_xr + (size_t)d * HC + c0);

    int st = g_rowptr[d];
    int en = g_rowptr[d + 1];

    float den = 0.f;
    float4 acc = {0.f, 0.f, 0.f, 0.f};

    int j = st;
    for (; j + 1 < en; j += 2) {
        // two independent index loads + gathers (MLP=2)
        int s0 = g_srcs[j + 0];
        int s1 = g_srcs[j + 1];
        float4 xl0 = *(const float4*)(g_xl + (size_t)s0 * HC + c0);
        float4 xl1 = *(const float4*)(g_xl + (size_t)s1 * HC + c0);
        const float4* eP = (const float4*)(g_eatt + (size_t)j * ED);

        float4 m0, m1;
        m0.x = xl0.x + xr4.x; m0.y = xl0.y + xr4.y;
        m0.z = xl0.z + xr4.z; m0.w = xl0.w + xr4.w;
        m1.x = xl1.x + xr4.x; m1.y = xl1.y + xr4.y;
        m1.z = xl1.z + xr4.z; m1.w = xl1.w + xr4.w;

#pragma unroll
        for (int q = 0; q < 4; q++) {
            float4 e0 = eP[q];          // edge j   attrs [4q..4q+3] (uniform LDG.128)
            float4 e1 = eP[q + 4];      // edge j+1
#pragma unroll
            for (int u = 0; u < 4; u++) {
                float4 wk = wreg[q * 4 + u];
                float a0 = (u == 0) ? e0.x : (u == 1) ? e0.y : (u == 2) ? e0.z : e0.w;
                float a1 = (u == 0) ? e1.x : (u == 1) ? e1.y : (u == 2) ? e1.z : e1.w;
                m0.x += a0 * wk.x; m0.y += a0 * wk.y;
                m0.z += a0 * wk.z; m0.w += a0 * wk.w;
                m1.x += a1 * wk.x; m1.y += a1 * wk.y;
                m1.z += a1 * wk.z; m1.w += a1 * wk.w;
            }
        }

#define LRELU4(mm) \
        mm.x = (mm.x > 0.f) ? mm.x : 0.2f * mm.x; \
        mm.y = (mm.y > 0.f) ? mm.y : 0.2f * mm.y; \
        mm.z = (mm.z > 0.f) ? mm.z : 0.2f * mm.z; \
        mm.w = (mm.w > 0.f) ? mm.w : 0.2f * mm.w;
        LRELU4(m0) LRELU4(m1)

        float p0 = m0.x * a4.x + m0.y * a4.y + m0.z * a4.z + m0.w * a4.w;
        float p1 = m1.x * a4.x + m1.y * a4.y + m1.z * a4.z + m1.w * a4.w;
        p0 += __shfl_xor_sync(MASK, p0, 1);
        p1 += __shfl_xor_sync(MASK, p1, 1);
        p0 += __shfl_xor_sync(MASK, p0, 2);
        p1 += __shfl_xor_sync(MASK, p1, 2);

        float e0v = __expf(p0);
        float e1v = __expf(p1);
        den += e0v + e1v;
        acc.x += e0v * xl0.x + e1v * xl1.x;
        acc.y += e0v * xl0.y + e1v * xl1.y;
        acc.z += e0v * xl0.z + e1v * xl1.z;
        acc.w += e0v * xl0.w + e1v * xl1.w;
    }

    if (j < en) {   // remainder edge
        int s = g_srcs[j];
        const float4* eP = (const float4*)(g_eatt + (size_t)j * ED);
        float4 xl4 = *(const float4*)(g_xl + (size_t)s * HC + c0);
        float4 m;
        m.x = xl4.x + xr4.x; m.y = xl4.y + xr4.y;
        m.z = xl4.z + xr4.z; m.w = xl4.w + xr4.w;
#pragma unroll
        for (int q = 0; q < 4; q++) {
            float4 ea = eP[q];
#pragma unroll
            for (int u = 0; u < 4; u++) {
                float av = (u == 0) ? ea.x : (u == 1) ? ea.y : (u == 2) ? ea.z : ea.w;
                float4 wk = wreg[q * 4 + u];
                m.x += av * wk.x; m.y += av * wk.y;
                m.z += av * wk.z; m.w += av * wk.w;
            }
        }
        LRELU4(m)
        float p = m.x * a4.x + m.y * a4.y + m.z * a4.z + m.w * a4.w;
        p += __shfl_xor_sync(MASK, p, 1);
        p += __shfl_xor_sync(MASK, p, 2);
        float a = __expf(p);
        den += a;
        acc.x += a * xl4.x;
        acc.y += a * xl4.y;
        acc.z += a * xl4.z;
        acc.w += a * xl4.w;
    }
#undef LRELU4

    float inv = 1.f / (den + 1e-16f);
    float4 b4 = *(const float4*)(bias + c0);
    float4 o;
    o.x = acc.x * inv + b4.x;
    o.y = acc.y * inv + b4.y;
    o.z = acc.z * inv + b4.z;
    o.w = acc.w * inv + b4.w;
    if (apply_relu) {
        o.x = fmaxf(o.x, 0.f);
        o.y = fmaxf(o.y, 0.f);
        o.z = fmaxf(o.z, 0.f);
        o.w = fmaxf(o.w, 0.f);
    }
    float* obuf = out_sel ? out : g_h;
    *(float4*)(obuf + (size_t)d * HC + c0) = o;
}

// ---------------- launch ----------------
extern "C" void kernel_launch(void* const* d_in, const int* in_sizes, int n_in,
                              void* d_out, int out_size) {
    int ix, iei, iea;
    int iwl[3], ibl[3], iwr[3], ibr[3], iwe[3], iatt[3], ibias[3];
    if (in_sizes[0] == NN * 128) {
        // insertion order: x, edge_index, edge_attr, {wl,bl,wr,br,we,att,bias}x3
        ix = 0; iei = 1; iea = 2;
        for (int l = 0; l < 3; l++) {
            int b = 3 + l * 7;
            iwl[l] = b + 0; ibl[l] = b + 1; iwr[l] = b + 2; ibr[l] = b + 3;
            iwe[l] = b + 4; iatt[l] = b + 5; ibias[l] = b + 6;
        }
    } else {
        // alphabetical: att1-3, b1l,b1r,b2l,b2r,b3l,b3r, bias1-3,
        //               edge_attr, edge_index, (w1e,w1l,w1r)x3, x
        for (int l = 0; l < 3; l++) {
            iatt[l]  = l;
            ibl[l]   = 3 + 2 * l;
            ibr[l]   = 4 + 2 * l;
            ibias[l] = 9 + l;
            iwe[l]   = 14 + 3 * l;
            iwl[l]   = 15 + 3 * l;
            iwr[l]   = 16 + 3 * l;
        }
        iea = 12; iei = 13; ix = 23;
    }

    const float* x      = (const float*)d_in[ix];
    const int*   eindex = (const int*)d_in[iei];     // [2,E] row-major
    const float* eattr  = (const float*)d_in[iea];
    const int* src = eindex;
    const int* dst = eindex + EE;
    float* out = (float*)d_out;

    int nb = (NN + 511) / 512;  // 196

    // launch order keeps gemm_lr layer 0 at index 3 (the ncu-captured launch)
    hist_kernel<<<(EE + 255) / 256, 256>>>(dst);                 // 0
    scan_a_kernel<<<nb, 512>>>();                                // 1
    scan_bc_kernel<<<nb, 512>>>(nb);                             // 2

    gemm_lr_kernel<<<NN / 32, 160>>>(                            // 3 (profiled)
        x, 0, 128,
        (const float*)d_in[iwl[0]], (const float*)d_in[ibl[0]],
        (const float*)d_in[iwr[0]], (const float*)d_in[ibr[0]]);

    fill_kernel<<<(EE + 255) / 256, 256>>>(src, dst, eattr);     // 4

    for (int l = 0; l < 3; l++) {
        const float* we_   = (const float*)d_in[iwe[l]];
        const float* att_  = (const float*)d_in[iatt[l]];
        const float* bias_ = (const float*)d_in[ibias[l]];

        if (l > 0) {
            gemm_lr_kernel<<<NN / 32, 160>>>(
                (const float*)nullptr, 1, HC,
                (const float*)d_in[iwl[l]], (const float*)d_in[ibl[l]],
                (const float*)d_in[iwr[l]], (const float*)d_in[ibr[l]]);
        }
        fused_attn_kernel<<<(NN + 7) / 8, 256>>>(we_, att_, bias_, out,
            (l == 2) ? 1 : 0, (l < 2) ? 1 : 0);
    }
}